// round 8
// baseline (speedup 1.0000x reference)
#include <cuda_runtime.h>

#define BN_EPS 1e-5f

// Scratch (allocation-free rule: __device__ globals)
__device__ __align__(16) float g_yT[8 * 64 * 64 * 64];   // (b, hy, w, o)  TRANSPOSED
__device__ __align__(16) float g_res[8 * 128 * 128];     // (b, h, w)
__device__ __align__(16) float g_wt2[64 * 64];           // w2 transposed [c][o]

// ---------------- f32x2 packed-FMA helpers (Blackwell dual-rate fp32) -------
typedef unsigned long long u64;

__device__ __forceinline__ u64 pack2(float lo, float hi) {
    u64 r;
    asm("mov.b64 %0, {%1, %2};" : "=l"(r) : "f"(lo), "f"(hi));
    return r;
}
__device__ __forceinline__ void unpack2(u64 v, float& lo, float& hi) {
    asm("mov.b64 {%0, %1}, %2;" : "=f"(lo), "=f"(hi) : "l"(v));
}
__device__ __forceinline__ void fma2(u64& d, u64 a, u64 b) {
    asm("fma.rn.f32x2 %0, %1, %2, %0;" : "+l"(d) : "l"(a), "l"(b));
}

__device__ __forceinline__ void cp_async16(void* smem_dst, const void* gptr) {
    unsigned sa = (unsigned)__cvta_generic_to_shared(smem_dst);
    asm volatile("cp.async.cg.shared.global [%0], [%1], 16;" :: "r"(sa), "l"(gptr));
}
__device__ __forceinline__ void cp_commit() {
    asm volatile("cp.async.commit_group;");
}
template <int N>
__device__ __forceinline__ void cp_wait() {
    asm volatile("cp.async.wait_group %0;" :: "n"(N));
}

// ---- Kernel A: res mean + conv1 + w2 transpose, one grid -------------------
__global__ void __launch_bounds__(256) prep_conv1_kernel(
    const float4* __restrict__ ref4, const float* __restrict__ x,
    const float* __restrict__ w1, const float* __restrict__ w2,
    const float* __restrict__ b1, const float* __restrict__ g1,
    const float* __restrict__ bt1, const float* __restrict__ m1,
    const float* __restrict__ v1)
{
    __shared__ __align__(16) float s_x[64 * 64];     // [c][w]
    __shared__ __align__(16) float s_wt[64 * 66];    // [c][o] padded (stride 66)
    __shared__ float s_A[64], s_B[64];

    int bid = blockIdx.x, t = threadIdx.x;

    if (bid < 512) {
        // ---- res path: high-MLP strided reduction ----
        int idx = bid * 256 + t;          // 4 threads per float4-pixel
        int quad = idx >> 2, q = idx & 3;
        int b = quad >> 12, p = quad & 4095;
        const float4* src = ref4 + (size_t)b * 262144 + (size_t)q * 16 * 4096 + p;
        float sx = 0.f, sy = 0.f, sz = 0.f, sw = 0.f;
#pragma unroll
        for (int c = 0; c < 16; c++) {
            float4 v = src[(size_t)c * 4096];
            sx += v.x; sy += v.y; sz += v.z; sw += v.w;
        }
#pragma unroll
        for (int m = 1; m <= 2; m <<= 1) {
            sx += __shfl_xor_sync(0xFFFFFFFFu, sx, m);
            sy += __shfl_xor_sync(0xFFFFFFFFu, sy, m);
            sz += __shfl_xor_sync(0xFFFFFFFFu, sz, m);
            sw += __shfl_xor_sync(0xFFFFFFFFu, sw, m);
        }
        if (q == 0) {
            const float f = 1.0f / 64.0f;
            ((float4*)g_res)[quad] = make_float4(sx * f, sy * f, sz * f, sw * f);
        }
        return;
    }
    if (bid >= 1024) {
        // ---- w2 transpose path ----
        int e0 = (bid - 1024) * 1024 + t;
#pragma unroll
        for (int k = 0; k < 4; k++) {
            int e = e0 + k * 256;
            int o = e >> 6, c = e & 63;
            g_wt2[c * 64 + o] = w2[e];
        }
        return;
    }

    // ---- conv1 path ----
    int blk = bid - 512;
    int h = blk & 63, b = blk >> 6;

    if (t < 64) {
        float sc = g1[t] * rsqrtf(v1[t] + BN_EPS);
        s_A[t] = sc;
        s_B[t] = b1[t] * sc + bt1[t] - m1[t] * sc;
    }
    const float* xrow = x + (size_t)b * 64 * 4096 + (size_t)h * 64;
    for (int i = t; i < 1024; i += 256) {
        int c = i >> 4, w4 = (i & 15) * 4;
        *(float4*)&s_x[c * 64 + w4] = *(const float4*)&xrow[(size_t)c * 4096 + w4];
    }
    for (int i = t; i < 4096; i += 256) {
        int o = i >> 6, c = i & 63;
        s_wt[c * 66 + o] = w1[i];
    }
    __syncthreads();

    int wg = t & 31, og = t >> 5;
    int w0 = wg * 2, o0 = og * 8;

    u64 acc[4][2];
#pragma unroll
    for (int i = 0; i < 4; i++)
#pragma unroll
        for (int j = 0; j < 2; j++) acc[i][j] = 0ull;

#pragma unroll 8
    for (int c = 0; c < 64; c++) {
        float2 rv = *(const float2*)&s_x[c * 64 + w0];
        u64 r0 = pack2(rv.x, rv.x);
        u64 r1 = pack2(rv.y, rv.y);
        const u64* wp = (const u64*)&s_wt[c * 66 + o0];
        u64 wv0 = wp[0], wv1 = wp[1], wv2 = wp[2], wv3 = wp[3];
        fma2(acc[0][0], wv0, r0); fma2(acc[0][1], wv0, r1);
        fma2(acc[1][0], wv1, r0); fma2(acc[1][1], wv1, r1);
        fma2(acc[2][0], wv2, r0); fma2(acc[2][1], wv2, r1);
        fma2(acc[3][0], wv3, r0); fma2(acc[3][1], wv3, r1);
    }

    // transposed store: g_yT[b][h][w][o], 8 consecutive o per w
    float* ytbase = g_yT + ((size_t)(b * 64 + h)) * 4096;
#pragma unroll
    for (int j = 0; j < 2; j++) {
        float val[8];
#pragma unroll
        for (int i = 0; i < 4; i++) {
            int oA = o0 + 2 * i, oB = oA + 1;
            float lo, hi;
            unpack2(acc[i][j], lo, hi);
            val[2 * i]     = fmaxf(lo * s_A[oA] + s_B[oA], 0.f);
            val[2 * i + 1] = fmaxf(hi * s_A[oB] + s_B[oB], 0.f);
        }
        float* dst = ytbase + (size_t)(w0 + j) * 64 + o0;
        *(float4*)dst       = make_float4(val[0], val[1], val[2], val[3]);
        *(float4*)(dst + 4) = make_float4(val[4], val[5], val[6], val[7]);
    }
}

// ---------------- Kernel B: fused mask + aggregate + conv2 ------------------
// smem: buf0 2048 | buf1 2048 | wt 4096 | yT 2*4608 (stride 72) | res 396 | A,B 128
#define YT_STRIDE 72
#define YT_ROW    (64 * YT_STRIDE)          // 4608
#define FUSE_SMEM_FLOATS (2048 + 2048 + 4096 + 2 * YT_ROW + 396 + 64 + 64)
#define FUSE_SMEM_BYTES  (FUSE_SMEM_FLOATS * 4)

__global__ void __launch_bounds__(256, 3) fuse_kernel(
    const float* __restrict__ ref,
    const float* __restrict__ b2,  const float* __restrict__ g2,
    const float* __restrict__ bt2, const float* __restrict__ m2,
    const float* __restrict__ v2,  float* __restrict__ out)
{
    extern __shared__ float sm[];
    float* s_buf[2] = { sm, sm + 2048 };
    float* s_wt  = sm + 4096;                 // 4096
    float* s_yT  = sm + 8192;                 // 2 * 4608
    float* s_res = sm + 8192 + 2 * YT_ROW;    // 396
    float* s_A   = s_res + 396;               // 64
    float* s_B   = s_A + 64;                  // 64

    int h = blockIdx.x, b = blockIdx.y;
    int t = threadIdx.x;

    const float* rrow = ref + (size_t)b * 64 * 16384 + (size_t)h * 128;

    auto issue = [&](int k, float* buf) {
#pragma unroll
        for (int r = 0; r < 2; r++) {
            int i = t + r * 256;                      // 512 float4s per chunk
            int cl = i >> 5, w4 = (i & 31) << 2;
            cp_async16(buf + cl * 128 + w4,
                       rrow + (size_t)(k * 16 + cl) * 16384 + w4);
        }
        cp_commit();
    };

    issue(0, s_buf[0]);                               // g0

    // g1: transposed w2 (contiguous)
#pragma unroll
    for (int r = 0; r < 4; r++) {
        int i = t + r * 256;
        cp_async16(s_wt + i * 4, g_wt2 + i * 4);
    }
    cp_commit();

    issue(1, s_buf[1]);                               // g2

    // g3: two yT rows (b, r, w, o) -> smem stride-72 padded
    int r0 = (h - 1) >> 1; if (r0 < 0) r0 = 0;
    int r1 = (h + 1) >> 1; if (r1 > 63) r1 = 63;
    {
        const float* src0 = g_yT + ((size_t)(b * 64 + r0)) * 4096;
        const float* src1 = g_yT + ((size_t)(b * 64 + r1)) * 4096;
#pragma unroll
        for (int r = 0; r < 4; r++) {
            int i = t + r * 256;                      // 1024 chunks per row
            int w = i >> 4, oc = (i & 15) * 4;
            cp_async16(&s_yT[w * YT_STRIDE + oc],           src0 + i * 4);
            cp_async16(&s_yT[YT_ROW + w * YT_STRIDE + oc],  src1 + i * 4);
        }
        cp_commit();
    }

    if (t < 64) {
        float sc = g2[t] * rsqrtf(v2[t] + BN_EPS);
        s_A[t] = sc;
        s_B[t] = b2[t] * sc + bt2[t] - m2[t] * sc;
    }
    for (int i = t; i < 3 * 132; i += 256) {
        int j = i / 132, col = i % 132;
        int rr = h - 1 + j, wc = col - 1;
        float v = 0.f;
        if (col < 130 && rr >= 0 && rr < 128 && wc >= 0 && wc < 128)
            v = g_res[((size_t)b * 128 + rr) * 128 + wc];
        s_res[i] = v;
    }

    // ---- new lane mapping: warp owns 16 w x 64 o; thread = 4 w x 8 o ----
    int wid = t >> 5, l = t & 31;
    int og = l >> 2, wq = l & 3;
    int w0 = wid * 16 + wq * 4;
    int o0 = og * 8;

    u64 acc[4][4];                     // [o-pair i][w j]
#pragma unroll
    for (int i = 0; i < 4; i++)
#pragma unroll
        for (int j = 0; j < 4; j++) acc[i][j] = 0ull;

#pragma unroll
    for (int k = 0; k < 4; k++) {
        if (k == 0)      cp_wait<2>();
        else if (k == 1) cp_wait<2>();
        else if (k == 2) cp_wait<1>();
        else             cp_wait<0>();
        __syncthreads();
        const float* bufp = s_buf[k & 1];
#pragma unroll
        for (int cl = 0; cl < 16; cl++) {
            int c = k * 16 + cl;
            float4 rv = *(const float4*)&bufp[cl * 128 + w0];   // 4-chunk bcast
            u64 rr0 = pack2(rv.x, rv.x);
            u64 rr1 = pack2(rv.y, rv.y);
            u64 rr2 = pack2(rv.z, rv.z);
            u64 rr3 = pack2(rv.w, rv.w);
            const u64* wp = (const u64*)&s_wt[c * 64 + o0];     // 2x LDS.128
            u64 wv0 = wp[0], wv1 = wp[1], wv2 = wp[2], wv3 = wp[3];
            fma2(acc[0][0], wv0, rr0); fma2(acc[0][1], wv0, rr1); fma2(acc[0][2], wv0, rr2); fma2(acc[0][3], wv0, rr3);
            fma2(acc[1][0], wv1, rr0); fma2(acc[1][1], wv1, rr1); fma2(acc[1][2], wv1, rr2); fma2(acc[1][3], wv1, rr3);
            fma2(acc[2][0], wv2, rr0); fma2(acc[2][1], wv2, rr1); fma2(acc[2][2], wv2, rr2); fma2(acc[2][3], wv2, rr3);
            fma2(acc[3][0], wv3, rr0); fma2(acc[3][1], wv3, rr1); fma2(acc[3][2], wv3, rr2); fma2(acc[3][3], wv3, rr3);
        }
        if (k + 2 < 4) {
            __syncthreads();
            issue(k + 2, s_buf[k & 1]);
        }
    }

    // ---- mask weights for this thread's 4 w ----
    int rs0 = 1 - (h & 1);
    float W00a[4], W01a[4], W10a[4], W11a[4];
#pragma unroll
    for (int j = 0; j < 4; j++) {
        int w = w0 + j;
        float ur[9];
        float sum9 = 0.f;
#pragma unroll
        for (int di = 0; di < 3; di++)
#pragma unroll
            for (int dj = 0; dj < 3; dj++) {
                float v = s_res[di * 132 + w + dj];
                ur[di * 3 + dj] = v;
                sum9 += v;
            }
        float ua = sum9 * (1.f / 9.f);
        bool ui = (ur[4] - ua) > 0.f;
        float W[2][2] = {{0.f, 0.f}, {0.f, 0.f}};
        float den = 1e-6f;
        int cs0 = 1 - (w & 1);
#pragma unroll
        for (int di = 0; di < 3; di++) {
            int hh = h + di - 1;
            bool rvalid = (hh >= 0) && (hh < 128);
            int rsel = (di == 0) ? 0 : ((di == 2) ? 1 : rs0);
#pragma unroll
            for (int dj = 0; dj < 3; dj++) {
                int ww = w + dj - 1;
                bool cvalid = (ww >= 0) && (ww < 128);
                bool up = (ur[di * 3 + dj] - ua) > 0.f;
                float mk = (up == ui) ? 1.f : 0.f;
                den += mk;
                int csel = (dj == 0) ? 0 : ((dj == 2) ? 1 : cs0);
                if (rvalid && cvalid) W[rsel][csel] += mk;
            }
        }
        float rd = 1.0f / den;
        W00a[j] = W[0][0] * rd; W01a[j] = W[0][1] * rd;
        W10a[j] = W[1][0] * rd; W11a[j] = W[1][1] * rd;
    }

    // thread's 4 y columns: {2Q-1, 2Q, 2Q+1, 2Q+2} clamped; per-j tap indices
    int Q = w0 >> 2;
    int cols[4];
    cols[0] = (2 * Q - 1 < 0) ? 0 : 2 * Q - 1;
    cols[1] = 2 * Q;
    cols[2] = 2 * Q + 1;
    cols[3] = (2 * Q + 2 > 63) ? 63 : 2 * Q + 2;
    const int c0i[4] = {0, 1, 1, 2};
    const int c1i[4] = {1, 2, 2, 3};

    // ---- epilogue in o-pair quarters: vector y loads, float4 stores ----
    float* outrow = out + (size_t)b * 64 * 16384 + (size_t)h * 128;
#pragma unroll
    for (int p = 0; p < 4; p++) {
        int ob = o0 + 2 * p;
        float2 yv[2][4];                 // [row][col]
#pragma unroll
        for (int cc = 0; cc < 4; cc++) {
            yv[0][cc] = *(const float2*)&s_yT[cols[cc] * YT_STRIDE + ob];
            yv[1][cc] = *(const float2*)&s_yT[YT_ROW + cols[cc] * YT_STRIDE + ob];
        }
        float rlo[4], rhi[4];
#pragma unroll
        for (int j = 0; j < 4; j++) {
            float lo, hi;
            unpack2(acc[p][j], lo, hi);
            int oA = ob, oB = ob + 1;
            float convA = fmaxf(lo * s_A[oA] + s_B[oA], 0.f);
            float convB = fmaxf(hi * s_A[oB] + s_B[oB], 0.f);
            float2 a0 = yv[0][c0i[j]], a1 = yv[0][c1i[j]];
            float2 b0 = yv[1][c0i[j]], b1 = yv[1][c1i[j]];
            rlo[j] = W00a[j] * a0.x + W01a[j] * a1.x
                   + W10a[j] * b0.x + W11a[j] * b1.x + convA;
            rhi[j] = W00a[j] * a0.y + W01a[j] * a1.y
                   + W10a[j] * b0.y + W11a[j] * b1.y + convB;
        }
        *(float4*)&outrow[(size_t)ob * 16384 + w0] =
            make_float4(rlo[0], rlo[1], rlo[2], rlo[3]);
        *(float4*)&outrow[(size_t)(ob + 1) * 16384 + w0] =
            make_float4(rhi[0], rhi[1], rhi[2], rhi[3]);
    }
}

// ---------------------------------------------------------------------------
extern "C" void kernel_launch(void* const* d_in, const int* in_sizes, int n_in,
                              void* d_out, int out_size) {
    (void)in_sizes; (void)n_in; (void)out_size;
    const float* x   = (const float*)d_in[0];
    const float* ref = (const float*)d_in[1];
    const float* w1  = (const float*)d_in[2];
    const float* b1  = (const float*)d_in[3];
    const float* g1  = (const float*)d_in[4];
    const float* bt1 = (const float*)d_in[5];
    const float* m1  = (const float*)d_in[6];
    const float* v1  = (const float*)d_in[7];
    const float* w2  = (const float*)d_in[8];
    const float* b2  = (const float*)d_in[9];
    const float* g2  = (const float*)d_in[10];
    const float* bt2 = (const float*)d_in[11];
    const float* m2  = (const float*)d_in[12];
    const float* v2  = (const float*)d_in[13];
    float* out = (float*)d_out;

    cudaFuncSetAttribute(fuse_kernel, cudaFuncAttributeMaxDynamicSharedMemorySize,
                         FUSE_SMEM_BYTES);

    prep_conv1_kernel<<<1028, 256>>>((const float4*)ref, x, w1, w2,
                                     b1, g1, bt1, m1, v1);
    fuse_kernel<<<dim3(128, 8), 256, FUSE_SMEM_BYTES>>>(ref, b2, g2, bt2, m2, v2, out);
}

// round 10
// speedup vs baseline: 1.0094x; 1.0094x over previous
#include <cuda_runtime.h>

#define BN_EPS 1e-5f

// Scratch (allocation-free rule: __device__ globals)
__device__ __align__(16) float g_yT[8 * 64 * 64 * 64];   // (b, hy, w, o)  TRANSPOSED
__device__ __align__(16) float g_res[8 * 128 * 128];     // (b, h, w)
__device__ __align__(16) float g_wt2[64 * 64];           // w2 transposed [c][o]

// ---------------- f32x2 packed-FMA helpers (Blackwell dual-rate fp32) -------
typedef unsigned long long u64;

__device__ __forceinline__ u64 pack2(float lo, float hi) {
    u64 r;
    asm("mov.b64 %0, {%1, %2};" : "=l"(r) : "f"(lo), "f"(hi));
    return r;
}
__device__ __forceinline__ void unpack2(u64 v, float& lo, float& hi) {
    asm("mov.b64 {%0, %1}, %2;" : "=f"(lo), "=f"(hi) : "l"(v));
}
__device__ __forceinline__ void fma2(u64& d, u64 a, u64 b) {
    asm("fma.rn.f32x2 %0, %1, %2, %0;" : "+l"(d) : "l"(a), "l"(b));
}

__device__ __forceinline__ void cp_async16(void* smem_dst, const void* gptr) {
    unsigned sa = (unsigned)__cvta_generic_to_shared(smem_dst);
    asm volatile("cp.async.cg.shared.global [%0], [%1], 16;" :: "r"(sa), "l"(gptr));
}
__device__ __forceinline__ void cp_commit() {
    asm volatile("cp.async.commit_group;");
}
template <int N>
__device__ __forceinline__ void cp_wait() {
    asm volatile("cp.async.wait_group %0;" :: "n"(N));
}

// ---- Kernel A: res mean + conv1 + w2 transpose, one grid -------------------
__global__ void __launch_bounds__(256) prep_conv1_kernel(
    const float4* __restrict__ ref4, const float* __restrict__ x,
    const float* __restrict__ w1, const float* __restrict__ w2,
    const float* __restrict__ b1, const float* __restrict__ g1,
    const float* __restrict__ bt1, const float* __restrict__ m1,
    const float* __restrict__ v1)
{
    __shared__ __align__(16) float s_x[64 * 64];     // [c][w]
    __shared__ __align__(16) float s_wt[64 * 66];    // [c][o] padded; reused as stage
    __shared__ float s_A[64], s_B[64];

    int bid = blockIdx.x, t = threadIdx.x;

    if (bid < 512) {
        // ---- res path: high-MLP strided reduction ----
        int idx = bid * 256 + t;          // 4 threads per float4-pixel
        int quad = idx >> 2, q = idx & 3;
        int b = quad >> 12, p = quad & 4095;
        const float4* src = ref4 + (size_t)b * 262144 + (size_t)q * 16 * 4096 + p;
        float sx = 0.f, sy = 0.f, sz = 0.f, sw = 0.f;
#pragma unroll
        for (int c = 0; c < 16; c++) {
            float4 v = src[(size_t)c * 4096];
            sx += v.x; sy += v.y; sz += v.z; sw += v.w;
        }
#pragma unroll
        for (int m = 1; m <= 2; m <<= 1) {
            sx += __shfl_xor_sync(0xFFFFFFFFu, sx, m);
            sy += __shfl_xor_sync(0xFFFFFFFFu, sy, m);
            sz += __shfl_xor_sync(0xFFFFFFFFu, sz, m);
            sw += __shfl_xor_sync(0xFFFFFFFFu, sw, m);
        }
        if (q == 0) {
            const float f = 1.0f / 64.0f;
            ((float4*)g_res)[quad] = make_float4(sx * f, sy * f, sz * f, sw * f);
        }
        return;
    }
    if (bid >= 1024) {
        // ---- w2 transpose path ----
        int e0 = (bid - 1024) * 1024 + t;
#pragma unroll
        for (int k = 0; k < 4; k++) {
            int e = e0 + k * 256;
            int o = e >> 6, c = e & 63;
            g_wt2[c * 64 + o] = w2[e];
        }
        return;
    }

    // ---- conv1 path ----
    int blk = bid - 512;
    int h = blk & 63, b = blk >> 6;

    if (t < 64) {
        float sc = g1[t] * rsqrtf(v1[t] + BN_EPS);
        s_A[t] = sc;
        s_B[t] = b1[t] * sc + bt1[t] - m1[t] * sc;
    }
    const float* xrow = x + (size_t)b * 64 * 4096 + (size_t)h * 64;
    for (int i = t; i < 1024; i += 256) {
        int c = i >> 4, w4 = (i & 15) * 4;
        *(float4*)&s_x[c * 64 + w4] = *(const float4*)&xrow[(size_t)c * 4096 + w4];
    }
    for (int i = t; i < 4096; i += 256) {
        int o = i >> 6, c = i & 63;
        s_wt[c * 66 + o] = w1[i];
    }
    __syncthreads();

    int wg = t & 31, og = t >> 5;
    int w0 = wg * 2, o0 = og * 8;

    u64 acc[4][2];
#pragma unroll
    for (int i = 0; i < 4; i++)
#pragma unroll
        for (int j = 0; j < 2; j++) acc[i][j] = 0ull;

#pragma unroll 8
    for (int c = 0; c < 64; c++) {
        float2 rv = *(const float2*)&s_x[c * 64 + w0];
        u64 r0 = pack2(rv.x, rv.x);
        u64 r1 = pack2(rv.y, rv.y);
        const u64* wp = (const u64*)&s_wt[c * 66 + o0];
        u64 wv0 = wp[0], wv1 = wp[1], wv2 = wp[2], wv3 = wp[3];
        fma2(acc[0][0], wv0, r0); fma2(acc[0][1], wv0, r1);
        fma2(acc[1][0], wv1, r0); fma2(acc[1][1], wv1, r1);
        fma2(acc[2][0], wv2, r0); fma2(acc[2][1], wv2, r1);
        fma2(acc[3][0], wv3, r0); fma2(acc[3][1], wv3, r1);
    }
    __syncthreads();              // all mainloop smem reads done

    // stage [w][o] into s_wt (stride 66) using float2 (8B-aligned: idx even)
    float* s_stage = s_wt;
#pragma unroll
    for (int j = 0; j < 2; j++) {
        int wrow = (w0 + j) * 66;
#pragma unroll
        for (int i = 0; i < 4; i++) {
            int oA = o0 + 2 * i, oB = oA + 1;
            float lo, hi;
            unpack2(acc[i][j], lo, hi);
            float vA = fmaxf(lo * s_A[oA] + s_B[oA], 0.f);
            float vB = fmaxf(hi * s_A[oB] + s_B[oB], 0.f);
            *(float2*)&s_stage[wrow + oA] = make_float2(vA, vB);
        }
    }
    __syncthreads();

    // coalesced STG: g_yT[b][h][w][o] via float2 (one warp covers a 256B w-row)
    float* ytbase = g_yT + ((size_t)(b * 64 + h)) * 4096;
    for (int i = t; i < 2048; i += 256) {
        int w = i >> 5, o2 = (i & 31) * 2;
        *(float2*)&ytbase[w * 64 + o2] = *(const float2*)&s_stage[w * 66 + o2];
    }
}

// ---------------- Kernel B: fused mask + aggregate + conv2 ------------------
// 128 threads/block; thread tile = 8 o x 8 w; block = 64 o x 128 w (one h-row).
// smem: buf0 2048 | buf1 2048 | wt 4096 | yT 2*4608 (stride 72) | res 396 | A,B 128
#define YT_STRIDE 72
#define YT_ROW    (64 * YT_STRIDE)          // 4608
#define FUSE_SMEM_FLOATS (2048 + 2048 + 4096 + 2 * YT_ROW + 396 + 64 + 64)
#define FUSE_SMEM_BYTES  (FUSE_SMEM_FLOATS * 4)

__global__ void __launch_bounds__(128) fuse_kernel(
    const float* __restrict__ ref,
    const float* __restrict__ b2,  const float* __restrict__ g2,
    const float* __restrict__ bt2, const float* __restrict__ m2,
    const float* __restrict__ v2,  float* __restrict__ out)
{
    extern __shared__ float sm[];
    float* s_buf[2] = { sm, sm + 2048 };
    float* s_wt  = sm + 4096;                 // 4096
    float* s_yT  = sm + 8192;                 // 2 * 4608
    float* s_res = sm + 8192 + 2 * YT_ROW;    // 396
    float* s_A   = s_res + 396;               // 64
    float* s_B   = s_A + 64;                  // 64

    int h = blockIdx.x, b = blockIdx.y;
    int t = threadIdx.x;

    const float* rrow = ref + (size_t)b * 64 * 16384 + (size_t)h * 128;

    auto issue = [&](int k, float* buf) {
#pragma unroll
        for (int r = 0; r < 4; r++) {
            int i = t + r * 128;                      // 512 float4s per chunk
            int cl = i >> 5, w4 = (i & 31) << 2;
            cp_async16(buf + cl * 128 + w4,
                       rrow + (size_t)(k * 16 + cl) * 16384 + w4);
        }
        cp_commit();
    };

    issue(0, s_buf[0]);                               // g0

    // g1: transposed w2 (contiguous)
#pragma unroll
    for (int r = 0; r < 8; r++) {
        int i = t + r * 128;
        cp_async16(s_wt + i * 4, g_wt2 + i * 4);
    }
    cp_commit();

    issue(1, s_buf[1]);                               // g2

    // g3: two yT rows (b, r, w, o) -> smem stride-72 padded
    int r0 = (h - 1) >> 1; if (r0 < 0) r0 = 0;
    int r1 = (h + 1) >> 1; if (r1 > 63) r1 = 63;
    {
        const float* src0 = g_yT + ((size_t)(b * 64 + r0)) * 4096;
        const float* src1 = g_yT + ((size_t)(b * 64 + r1)) * 4096;
#pragma unroll
        for (int r = 0; r < 8; r++) {
            int i = t + r * 128;                      // 1024 chunks per row
            int w = i >> 4, oc = (i & 15) * 4;
            cp_async16(&s_yT[w * YT_STRIDE + oc],           src0 + i * 4);
            cp_async16(&s_yT[YT_ROW + w * YT_STRIDE + oc],  src1 + i * 4);
        }
        cp_commit();
    }

    if (t < 64) {
        float sc = g2[t] * rsqrtf(v2[t] + BN_EPS);
        s_A[t] = sc;
        s_B[t] = b2[t] * sc + bt2[t] - m2[t] * sc;
    }
    for (int i = t; i < 3 * 132; i += 128) {
        int j = i / 132, col = i % 132;
        int rr = h - 1 + j, wc = col - 1;
        float v = 0.f;
        if (col < 130 && rr >= 0 && rr < 128 && wc >= 0 && wc < 128)
            v = g_res[((size_t)b * 128 + rr) * 128 + wc];
        s_res[i] = v;
    }

    // ---- lane mapping: og = lane&7 (full-wavefront weight LDS), wq = lane>>3
    int wid = t >> 5, l = t & 31;
    int og = l & 7, wq = l >> 3;
    int w0 = wid * 32 + wq * 8;          // 8 w per thread
    int o0 = og * 8;                     // 8 o per thread

    u64 acc[4][8];                       // [o-pair][w]
#pragma unroll
    for (int i = 0; i < 4; i++)
#pragma unroll
        for (int j = 0; j < 8; j++) acc[i][j] = 0ull;

#pragma unroll
    for (int k = 0; k < 4; k++) {
        if (k == 0)      cp_wait<2>();
        else if (k == 1) cp_wait<2>();
        else if (k == 2) cp_wait<1>();
        else             cp_wait<0>();
        __syncthreads();
        const float* bufp = s_buf[k & 1];
#pragma unroll
        for (int cl = 0; cl < 16; cl++) {
            int c = k * 16 + cl;
            float4 ra = *(const float4*)&bufp[cl * 128 + w0];
            float4 rb = *(const float4*)&bufp[cl * 128 + w0 + 4];
            u64 rr[8];
            rr[0] = pack2(ra.x, ra.x); rr[1] = pack2(ra.y, ra.y);
            rr[2] = pack2(ra.z, ra.z); rr[3] = pack2(ra.w, ra.w);
            rr[4] = pack2(rb.x, rb.x); rr[5] = pack2(rb.y, rb.y);
            rr[6] = pack2(rb.z, rb.z); rr[7] = pack2(rb.w, rb.w);
            const u64* wp = (const u64*)&s_wt[c * 64 + o0];
            u64 wv0 = wp[0], wv1 = wp[1], wv2 = wp[2], wv3 = wp[3];
#pragma unroll
            for (int j = 0; j < 8; j++) {
                fma2(acc[0][j], wv0, rr[j]);
                fma2(acc[1][j], wv1, rr[j]);
                fma2(acc[2][j], wv2, rr[j]);
                fma2(acc[3][j], wv3, rr[j]);
            }
        }
        if (k + 2 < 4) {
            __syncthreads();
            issue(k + 2, s_buf[k & 1]);
        }
    }

    // ---- mask weights for this thread's 8 w ----
    int rs0 = 1 - (h & 1);
    float W00a[8], W01a[8], W10a[8], W11a[8];
#pragma unroll
    for (int j = 0; j < 8; j++) {
        int w = w0 + j;
        float ur[9];
        float sum9 = 0.f;
#pragma unroll
        for (int di = 0; di < 3; di++)
#pragma unroll
            for (int dj = 0; dj < 3; dj++) {
                float v = s_res[di * 132 + w + dj];
                ur[di * 3 + dj] = v;
                sum9 += v;
            }
        float ua = sum9 * (1.f / 9.f);
        bool ui = (ur[4] - ua) > 0.f;
        float W[2][2] = {{0.f, 0.f}, {0.f, 0.f}};
        float den = 1e-6f;
        int cs0 = 1 - (w & 1);
#pragma unroll
        for (int di = 0; di < 3; di++) {
            int hh = h + di - 1;
            bool rvalid = (hh >= 0) && (hh < 128);
            int rsel = (di == 0) ? 0 : ((di == 2) ? 1 : rs0);
#pragma unroll
            for (int dj = 0; dj < 3; dj++) {
                int ww = w + dj - 1;
                bool cvalid = (ww >= 0) && (ww < 128);
                bool up = (ur[di * 3 + dj] - ua) > 0.f;
                float mk = (up == ui) ? 1.f : 0.f;
                den += mk;
                int csel = (dj == 0) ? 0 : ((dj == 2) ? 1 : cs0);
                if (rvalid && cvalid) W[rsel][csel] += mk;
            }
        }
        float rd = 1.0f / den;
        W00a[j] = W[0][0] * rd; W01a[j] = W[0][1] * rd;
        W10a[j] = W[1][0] * rd; W11a[j] = W[1][1] * rd;
    }

    // y columns for an 8-w tile: cols w0/2-1 .. w0/2+4 (clamped) = 6 columns
    int cols[6];
#pragma unroll
    for (int kk = 0; kk < 6; kk++) {
        int c = (w0 >> 1) - 1 + kk;
        cols[kk] = (c < 0) ? 0 : ((c > 63) ? 63 : c);
    }
    const int c0i[8] = {0, 1, 1, 2, 2, 3, 3, 4};
    const int c1i[8] = {1, 2, 2, 3, 3, 4, 4, 5};

    // ---- epilogue in o-pair quarters: vector y loads, float4 stores ----
    float* outrow = out + (size_t)b * 64 * 16384 + (size_t)h * 128;
#pragma unroll
    for (int p = 0; p < 4; p++) {
        int ob = o0 + 2 * p;
        float2 yv[2][6];                 // [row][col]
#pragma unroll
        for (int cc = 0; cc < 6; cc++) {
            yv[0][cc] = *(const float2*)&s_yT[cols[cc] * YT_STRIDE + ob];
            yv[1][cc] = *(const float2*)&s_yT[YT_ROW + cols[cc] * YT_STRIDE + ob];
        }
        float rlo[8], rhi[8];
        int oA = ob, oB = ob + 1;
        float AA = s_A[oA], BA = s_B[oA];
        float AB = s_A[oB], BB = s_B[oB];
#pragma unroll
        for (int j = 0; j < 8; j++) {
            float lo, hi;
            unpack2(acc[p][j], lo, hi);
            float convA = fmaxf(lo * AA + BA, 0.f);
            float convB = fmaxf(hi * AB + BB, 0.f);
            float2 a0 = yv[0][c0i[j]], a1 = yv[0][c1i[j]];
            float2 b0 = yv[1][c0i[j]], b1 = yv[1][c1i[j]];
            rlo[j] = W00a[j] * a0.x + W01a[j] * a1.x
                   + W10a[j] * b0.x + W11a[j] * b1.x + convA;
            rhi[j] = W00a[j] * a0.y + W01a[j] * a1.y
                   + W10a[j] * b0.y + W11a[j] * b1.y + convB;
        }
        *(float4*)&outrow[(size_t)oA * 16384 + w0]     = make_float4(rlo[0], rlo[1], rlo[2], rlo[3]);
        *(float4*)&outrow[(size_t)oA * 16384 + w0 + 4] = make_float4(rlo[4], rlo[5], rlo[6], rlo[7]);
        *(float4*)&outrow[(size_t)oB * 16384 + w0]     = make_float4(rhi[0], rhi[1], rhi[2], rhi[3]);
        *(float4*)&outrow[(size_t)oB * 16384 + w0 + 4] = make_float4(rhi[4], rhi[5], rhi[6], rhi[7]);
    }
}

// ---------------------------------------------------------------------------
extern "C" void kernel_launch(void* const* d_in, const int* in_sizes, int n_in,
                              void* d_out, int out_size) {
    (void)in_sizes; (void)n_in; (void)out_size;
    const float* x   = (const float*)d_in[0];
    const float* ref = (const float*)d_in[1];
    const float* w1  = (const float*)d_in[2];
    const float* b1  = (const float*)d_in[3];
    const float* g1  = (const float*)d_in[4];
    const float* bt1 = (const float*)d_in[5];
    const float* m1  = (const float*)d_in[6];
    const float* v1  = (const float*)d_in[7];
    const float* w2  = (const float*)d_in[8];
    const float* b2  = (const float*)d_in[9];
    const float* g2  = (const float*)d_in[10];
    const float* bt2 = (const float*)d_in[11];
    const float* m2  = (const float*)d_in[12];
    const float* v2  = (const float*)d_in[13];
    float* out = (float*)d_out;

    cudaFuncSetAttribute(fuse_kernel, cudaFuncAttributeMaxDynamicSharedMemorySize,
                         FUSE_SMEM_BYTES);

    prep_conv1_kernel<<<1028, 256>>>((const float4*)ref, x, w1, w2,
                                     b1, g1, bt1, m1, v1);
    fuse_kernel<<<dim3(128, 8), 128, FUSE_SMEM_BYTES>>>(ref, b2, g2, bt2, m2, v2, out);
}

// round 11
// speedup vs baseline: 1.1604x; 1.1495x over previous
#include <cuda_runtime.h>

#define BN_EPS 1e-5f

// Scratch (allocation-free rule: __device__ globals)
__device__ __align__(16) float g_yT[8 * 64 * 64 * 64];   // (b, hy, w, o)  TRANSPOSED
__device__ __align__(16) float g_res[8 * 128 * 128];     // (b, h, w)
__device__ __align__(16) float g_wt2[64 * 64];           // w2 transposed [c][o]

// ---------------- f32x2 packed-FMA helpers (Blackwell dual-rate fp32) -------
typedef unsigned long long u64;

__device__ __forceinline__ u64 pack2(float lo, float hi) {
    u64 r;
    asm("mov.b64 %0, {%1, %2};" : "=l"(r) : "f"(lo), "f"(hi));
    return r;
}
__device__ __forceinline__ void unpack2(u64 v, float& lo, float& hi) {
    asm("mov.b64 {%0, %1}, %2;" : "=f"(lo), "=f"(hi) : "l"(v));
}
__device__ __forceinline__ void fma2(u64& d, u64 a, u64 b) {
    asm("fma.rn.f32x2 %0, %1, %2, %0;" : "+l"(d) : "l"(a), "l"(b));
}

__device__ __forceinline__ void cp_async16(void* smem_dst, const void* gptr) {
    unsigned sa = (unsigned)__cvta_generic_to_shared(smem_dst);
    asm volatile("cp.async.cg.shared.global [%0], [%1], 16;" :: "r"(sa), "l"(gptr));
}
__device__ __forceinline__ void cp_commit() {
    asm volatile("cp.async.commit_group;");
}
template <int N>
__device__ __forceinline__ void cp_wait() {
    asm volatile("cp.async.wait_group %0;" :: "n"(N));
}

// ---- Kernel A: res mean + conv1 + w2 transpose, one grid -------------------
__global__ void __launch_bounds__(256) prep_conv1_kernel(
    const float4* __restrict__ ref4, const float* __restrict__ x,
    const float* __restrict__ w1, const float* __restrict__ w2,
    const float* __restrict__ b1, const float* __restrict__ g1,
    const float* __restrict__ bt1, const float* __restrict__ m1,
    const float* __restrict__ v1)
{
    __shared__ __align__(16) float s_x[64 * 64];     // [c][w]
    __shared__ __align__(16) float s_wt[64 * 66];    // [c][o] padded; reused as stage
    __shared__ float s_A[64], s_B[64];

    int bid = blockIdx.x, t = threadIdx.x;

    if (bid < 512) {
        // ---- res path: high-MLP strided reduction ----
        int idx = bid * 256 + t;          // 4 threads per float4-pixel
        int quad = idx >> 2, q = idx & 3;
        int b = quad >> 12, p = quad & 4095;
        const float4* src = ref4 + (size_t)b * 262144 + (size_t)q * 16 * 4096 + p;
        float sx = 0.f, sy = 0.f, sz = 0.f, sw = 0.f;
#pragma unroll
        for (int c = 0; c < 16; c++) {
            float4 v = src[(size_t)c * 4096];
            sx += v.x; sy += v.y; sz += v.z; sw += v.w;
        }
#pragma unroll
        for (int m = 1; m <= 2; m <<= 1) {
            sx += __shfl_xor_sync(0xFFFFFFFFu, sx, m);
            sy += __shfl_xor_sync(0xFFFFFFFFu, sy, m);
            sz += __shfl_xor_sync(0xFFFFFFFFu, sz, m);
            sw += __shfl_xor_sync(0xFFFFFFFFu, sw, m);
        }
        if (q == 0) {
            const float f = 1.0f / 64.0f;
            ((float4*)g_res)[quad] = make_float4(sx * f, sy * f, sz * f, sw * f);
        }
        return;
    }
    if (bid >= 1024) {
        // ---- w2 transpose path ----
        int e0 = (bid - 1024) * 1024 + t;
#pragma unroll
        for (int k = 0; k < 4; k++) {
            int e = e0 + k * 256;
            int o = e >> 6, c = e & 63;
            g_wt2[c * 64 + o] = w2[e];
        }
        return;
    }

    // ---- conv1 path ----
    int blk = bid - 512;
    int h = blk & 63, b = blk >> 6;

    if (t < 64) {
        float sc = g1[t] * rsqrtf(v1[t] + BN_EPS);
        s_A[t] = sc;
        s_B[t] = b1[t] * sc + bt1[t] - m1[t] * sc;
    }
    const float* xrow = x + (size_t)b * 64 * 4096 + (size_t)h * 64;
    for (int i = t; i < 1024; i += 256) {
        int c = i >> 4, w4 = (i & 15) * 4;
        *(float4*)&s_x[c * 64 + w4] = *(const float4*)&xrow[(size_t)c * 4096 + w4];
    }
    for (int i = t; i < 4096; i += 256) {
        int o = i >> 6, c = i & 63;
        s_wt[c * 66 + o] = w1[i];
    }
    __syncthreads();

    int wg = t & 31, og = t >> 5;
    int w0 = wg * 2, o0 = og * 8;

    u64 acc[4][2];
#pragma unroll
    for (int i = 0; i < 4; i++)
#pragma unroll
        for (int j = 0; j < 2; j++) acc[i][j] = 0ull;

#pragma unroll 8
    for (int c = 0; c < 64; c++) {
        float2 rv = *(const float2*)&s_x[c * 64 + w0];
        u64 r0 = pack2(rv.x, rv.x);
        u64 r1 = pack2(rv.y, rv.y);
        const u64* wp = (const u64*)&s_wt[c * 66 + o0];
        u64 wv0 = wp[0], wv1 = wp[1], wv2 = wp[2], wv3 = wp[3];
        fma2(acc[0][0], wv0, r0); fma2(acc[0][1], wv0, r1);
        fma2(acc[1][0], wv1, r0); fma2(acc[1][1], wv1, r1);
        fma2(acc[2][0], wv2, r0); fma2(acc[2][1], wv2, r1);
        fma2(acc[3][0], wv3, r0); fma2(acc[3][1], wv3, r1);
    }
    __syncthreads();              // all mainloop smem reads done

    // stage [w][o] into s_wt (stride 66) using float2 (8B-aligned: idx even)
    float* s_stage = s_wt;
#pragma unroll
    for (int j = 0; j < 2; j++) {
        int wrow = (w0 + j) * 66;
#pragma unroll
        for (int i = 0; i < 4; i++) {
            int oA = o0 + 2 * i, oB = oA + 1;
            float lo, hi;
            unpack2(acc[i][j], lo, hi);
            float vA = fmaxf(lo * s_A[oA] + s_B[oA], 0.f);
            float vB = fmaxf(hi * s_A[oB] + s_B[oB], 0.f);
            *(float2*)&s_stage[wrow + oA] = make_float2(vA, vB);
        }
    }
    __syncthreads();

    // coalesced STG: g_yT[b][h][w][o] via float2
    float* ytbase = g_yT + ((size_t)(b * 64 + h)) * 4096;
    for (int i = t; i < 2048; i += 256) {
        int w = i >> 5, o2 = (i & 31) * 2;
        *(float2*)&ytbase[w * 64 + o2] = *(const float2*)&s_stage[w * 66 + o2];
    }
}

// ---------------- Kernel B: fused mask + aggregate + conv2 ------------------
// 256 threads/block; block handles TWO h-rows (h0 = 2*bx, h1 = h0+1).
// Thread tile = 8 o x 4 w x 2 rows. 2 blocks/SM.
// smem (floats): bufs 2(ping)x2(row)x2048 = 8192 | wt 4096 | yT 3*4608 | res 528 | A,B 128
#define YT_STRIDE 72
#define YT_ROW    (64 * YT_STRIDE)          // 4608
#define SM_WT     8192
#define SM_YT     (SM_WT + 4096)            // 12288
#define SM_RES    (SM_YT + 3 * YT_ROW)      // 26112
#define SM_A      (SM_RES + 528)
#define SM_B      (SM_A + 64)
#define FUSE_SMEM_FLOATS (SM_B + 64)        // 26768
#define FUSE_SMEM_BYTES  (FUSE_SMEM_FLOATS * 4)

__global__ void __launch_bounds__(256, 2) fuse_kernel(
    const float* __restrict__ ref,
    const float* __restrict__ b2,  const float* __restrict__ g2,
    const float* __restrict__ bt2, const float* __restrict__ m2,
    const float* __restrict__ v2,  float* __restrict__ out)
{
    extern __shared__ float sm[];
    float* s_wt  = sm + SM_WT;
    float* s_yT  = sm + SM_YT;
    float* s_res = sm + SM_RES;
    float* s_A   = sm + SM_A;
    float* s_B   = sm + SM_B;

    int h0 = blockIdx.x * 2, b = blockIdx.y;
    int t = threadIdx.x;

    const float* rrow0 = ref + (size_t)b * 64 * 16384 + (size_t)h0 * 128;

    // chunk k: 16 channels x 128 w for BOTH rows -> ping buffer (k&1)
    auto issue = [&](int k) {
        float* buf = sm + (k & 1) * 4096;
#pragma unroll
        for (int r = 0; r < 2; r++) {
            int i = t + r * 256;                      // 512 float4 per row
            int cl = i >> 5, w4 = (i & 31) << 2;
            const float* src = rrow0 + (size_t)(k * 16 + cl) * 16384 + w4;
            cp_async16(buf + cl * 128 + w4,        src);          // row h0
            cp_async16(buf + 2048 + cl * 128 + w4, src + 128);    // row h1
        }
        cp_commit();
    };

    issue(0);                                         // g0

    // g1: transposed w2 (contiguous)
#pragma unroll
    for (int r = 0; r < 4; r++) {
        int i = t + r * 256;
        cp_async16(s_wt + i * 4, g_wt2 + i * 4);
    }
    cp_commit();

    issue(1);                                         // g2

    // g3: three yT rows R-1, R, R+1 (clamped), R = h0/2
    int R = h0 >> 1;
    int yr[3];
    yr[0] = (R - 1 < 0) ? 0 : R - 1;
    yr[1] = R;
    yr[2] = (R + 1 > 63) ? 63 : R + 1;
    {
#pragma unroll
        for (int s = 0; s < 3; s++) {
            const float* src = g_yT + ((size_t)(b * 64 + yr[s])) * 4096;
#pragma unroll
            for (int r = 0; r < 4; r++) {
                int i = t + r * 256;                  // 1024 float4 per row
                int w = i >> 4, oc = (i & 15) * 4;
                cp_async16(&s_yT[s * YT_ROW + w * YT_STRIDE + oc], src + i * 4);
            }
        }
        cp_commit();
    }

    if (t < 64) {
        float sc = g2[t] * rsqrtf(v2[t] + BN_EPS);
        s_A[t] = sc;
        s_B[t] = b2[t] * sc + bt2[t] - m2[t] * sc;
    }
    // res rows h0-1 .. h0+2 (4 rows), zero padded cols
    for (int i = t; i < 4 * 132; i += 256) {
        int j = i / 132, col = i % 132;
        int rr = h0 - 1 + j, wc = col - 1;
        float v = 0.f;
        if (col < 130 && rr >= 0 && rr < 128 && wc >= 0 && wc < 128)
            v = g_res[((size_t)b * 128 + rr) * 128 + wc];
        s_res[i] = v;
    }

    // lane mapping (R7 style): og = l>>2 (8), wq = l&3 (4)
    int wid = t >> 5, l = t & 31;
    int og = l >> 2, wq = l & 3;
    int w0 = wid * 16 + wq * 4;          // 4 w per thread (x128 total)
    int o0 = og * 8;                     // 8 o per thread

    u64 acc[2][4][4];                    // [row][o-pair][w]
#pragma unroll
    for (int r = 0; r < 2; r++)
#pragma unroll
        for (int i = 0; i < 4; i++)
#pragma unroll
            for (int j = 0; j < 4; j++) acc[r][i][j] = 0ull;

#pragma unroll
    for (int k = 0; k < 4; k++) {
        if (k == 0)      cp_wait<2>();   // g0 + g1
        else if (k == 1) cp_wait<2>();   // g2
        else if (k == 2) cp_wait<1>();   // g3 + g4
        else             cp_wait<0>();   // g5
        __syncthreads();
        const float* bufp = sm + (k & 1) * 4096;
#pragma unroll
        for (int cl = 0; cl < 16; cl++) {
            int c = k * 16 + cl;
            const u64* wp = (const u64*)&s_wt[c * 64 + o0];
            u64 wv0 = wp[0], wv1 = wp[1], wv2 = wp[2], wv3 = wp[3];
#pragma unroll
            for (int r = 0; r < 2; r++) {
                float4 rv = *(const float4*)&bufp[r * 2048 + cl * 128 + w0];
                u64 rr0 = pack2(rv.x, rv.x);
                u64 rr1 = pack2(rv.y, rv.y);
                u64 rr2 = pack2(rv.z, rv.z);
                u64 rr3 = pack2(rv.w, rv.w);
                fma2(acc[r][0][0], wv0, rr0); fma2(acc[r][0][1], wv0, rr1);
                fma2(acc[r][0][2], wv0, rr2); fma2(acc[r][0][3], wv0, rr3);
                fma2(acc[r][1][0], wv1, rr0); fma2(acc[r][1][1], wv1, rr1);
                fma2(acc[r][1][2], wv1, rr2); fma2(acc[r][1][3], wv1, rr3);
                fma2(acc[r][2][0], wv2, rr0); fma2(acc[r][2][1], wv2, rr1);
                fma2(acc[r][2][2], wv2, rr2); fma2(acc[r][2][3], wv2, rr3);
                fma2(acc[r][3][0], wv3, rr0); fma2(acc[r][3][1], wv3, rr1);
                fma2(acc[r][3][2], wv3, rr2); fma2(acc[r][3][3], wv3, rr3);
            }
        }
        if (k + 2 < 4) {
            __syncthreads();
            issue(k + 2);                             // g4, g5
        }
    }

    // y column indices for this thread's 4 w (shared by both rows)
    int Q = w0 >> 2;
    int cols[4];
    cols[0] = (2 * Q - 1 < 0) ? 0 : 2 * Q - 1;
    cols[1] = 2 * Q;
    cols[2] = 2 * Q + 1;
    cols[3] = (2 * Q + 2 > 63) ? 63 : 2 * Q + 2;
    const int c0i[4] = {0, 1, 1, 2};
    const int c1i[4] = {1, 2, 2, 3};

    // ---- per-row epilogue: mask weights + aggregate + conv2 BN/ReLU --------
#pragma unroll
    for (int r = 0; r < 2; r++) {
        int h = h0 + r;                   // r=0 even (rs0=1), r=1 odd (rs0=0)
        const int rs0 = 1 - r;
        const float* resb = s_res + r * 132;          // rows j = di + r
        const float* ys0 = s_yT + (r + 0) * YT_ROW;   // slots (0,1) or (1,2)
        const float* ys1 = s_yT + (r + 1) * YT_ROW;

        float W00a[4], W01a[4], W10a[4], W11a[4];
#pragma unroll
        for (int j = 0; j < 4; j++) {
            int w = w0 + j;
            float ur[9];
            float sum9 = 0.f;
#pragma unroll
            for (int di = 0; di < 3; di++)
#pragma unroll
                for (int dj = 0; dj < 3; dj++) {
                    float v = resb[di * 132 + w + dj];
                    ur[di * 3 + dj] = v;
                    sum9 += v;
                }
            float ua = sum9 * (1.f / 9.f);
            bool ui = (ur[4] - ua) > 0.f;
            float W[2][2] = {{0.f, 0.f}, {0.f, 0.f}};
            float den = 1e-6f;
            int cs0 = 1 - (w & 1);
#pragma unroll
            for (int di = 0; di < 3; di++) {
                int hh = h + di - 1;
                bool rvalid = (hh >= 0) && (hh < 128);
                int rsel = (di == 0) ? 0 : ((di == 2) ? 1 : rs0);
#pragma unroll
                for (int dj = 0; dj < 3; dj++) {
                    int ww = w + dj - 1;
                    bool cvalid = (ww >= 0) && (ww < 128);
                    bool up = (ur[di * 3 + dj] - ua) > 0.f;
                    float mk = (up == ui) ? 1.f : 0.f;
                    den += mk;
                    int csel = (dj == 0) ? 0 : ((dj == 2) ? 1 : cs0);
                    if (rvalid && cvalid) W[rsel][csel] += mk;
                }
            }
            float rd = 1.0f / den;
            W00a[j] = W[0][0] * rd; W01a[j] = W[0][1] * rd;
            W10a[j] = W[1][0] * rd; W11a[j] = W[1][1] * rd;
        }

        float* outrow = out + (size_t)b * 64 * 16384 + (size_t)h * 128;
#pragma unroll
        for (int p = 0; p < 4; p++) {
            int ob = o0 + 2 * p;
            float2 yv0[4], yv1[4];
#pragma unroll
            for (int cc = 0; cc < 4; cc++) {
                yv0[cc] = *(const float2*)&ys0[cols[cc] * YT_STRIDE + ob];
                yv1[cc] = *(const float2*)&ys1[cols[cc] * YT_STRIDE + ob];
            }
            int oA = ob, oB = ob + 1;
            float AA = s_A[oA], BA = s_B[oA];
            float AB = s_A[oB], BB = s_B[oB];
            float rlo[4], rhi[4];
#pragma unroll
            for (int j = 0; j < 4; j++) {
                float lo, hi;
                unpack2(acc[r][p][j], lo, hi);
                float convA = fmaxf(lo * AA + BA, 0.f);
                float convB = fmaxf(hi * AB + BB, 0.f);
                float2 a0 = yv0[c0i[j]], a1 = yv0[c1i[j]];
                float2 b0 = yv1[c0i[j]], b1 = yv1[c1i[j]];
                rlo[j] = W00a[j] * a0.x + W01a[j] * a1.x
                       + W10a[j] * b0.x + W11a[j] * b1.x + convA;
                rhi[j] = W00a[j] * a0.y + W01a[j] * a1.y
                       + W10a[j] * b0.y + W11a[j] * b1.y + convB;
            }
            *(float4*)&outrow[(size_t)oA * 16384 + w0] =
                make_float4(rlo[0], rlo[1], rlo[2], rlo[3]);
            *(float4*)&outrow[(size_t)oB * 16384 + w0] =
                make_float4(rhi[0], rhi[1], rhi[2], rhi[3]);
        }
    }
}

// ---------------------------------------------------------------------------
extern "C" void kernel_launch(void* const* d_in, const int* in_sizes, int n_in,
                              void* d_out, int out_size) {
    (void)in_sizes; (void)n_in; (void)out_size;
    const float* x   = (const float*)d_in[0];
    const float* ref = (const float*)d_in[1];
    const float* w1  = (const float*)d_in[2];
    const float* b1  = (const float*)d_in[3];
    const float* g1  = (const float*)d_in[4];
    const float* bt1 = (const float*)d_in[5];
    const float* m1  = (const float*)d_in[6];
    const float* v1  = (const float*)d_in[7];
    const float* w2  = (const float*)d_in[8];
    const float* b2  = (const float*)d_in[9];
    const float* g2  = (const float*)d_in[10];
    const float* bt2 = (const float*)d_in[11];
    const float* m2  = (const float*)d_in[12];
    const float* v2  = (const float*)d_in[13];
    float* out = (float*)d_out;

    cudaFuncSetAttribute(fuse_kernel, cudaFuncAttributeMaxDynamicSharedMemorySize,
                         FUSE_SMEM_BYTES);

    prep_conv1_kernel<<<1028, 256>>>((const float4*)ref, x, w1, w2,
                                     b1, g1, bt1, m1, v1);
    fuse_kernel<<<dim3(64, 8), 256, FUSE_SMEM_BYTES>>>(ref, b2, g2, bt2, m2, v2, out);
}